// round 11
// baseline (speedup 1.0000x reference)
#include <cuda_runtime.h>
#include <cstdint>
#include <math.h>

// Problem dims
#define NE    16
#define NTOK  2048
#define DDIM  1024
#define HDIM  4096

// Static scratch (no allocs allowed)
__device__ float g_hidden[(size_t)NE * NTOK * HDIM];   // GEMM1 out (tf32-rounded values)
__device__ float g_xc [(size_t)NE * NTOK * DDIM];      // x  pre-rounded to tf32 (row-major)
__device__ float g_w1t[(size_t)NE * DDIM * HDIM];      // w1 -> [E,H,D] (n-major), tf32-rounded
__device__ float g_w2t[(size_t)NE * DDIM * HDIM];      // w2 -> [E,D,H] (n-major), tf32-rounded

__device__ __forceinline__ float rnaf(float x) {
    uint32_t r; asm("cvt.rna.tf32.f32 %0, %1;" : "=r"(r) : "f"(x));
    return __uint_as_float(r);
}
__device__ __forceinline__ float gelu_exact(float x) {
    return 0.5f * x * (1.0f + erff(x * 0.7071067811865476f));
}

#define LDSM_X4(d0, d1, d2, d3, addr) \
    asm volatile("ldmatrix.sync.aligned.m8n8.x4.shared.b16 {%0,%1,%2,%3}, [%4];" \
        : "=r"(d0), "=r"(d1), "=r"(d2), "=r"(d3) : "r"(addr))

// ===================== GEMM config =====================
// Block tile 128(M) x 128(N) x 32(K); 8 warps, warp tile 32x64; 2 CTAs/SM.
// 3-stage cp.async pipeline; next-next tile load issued BEFORE compute (real 2-tile slack).
// Tiles stored as [rows][32 tf32 = 128B] with 16B-granule swizzle:
//   granule' = granule ^ (row % 8)
constexpr int BM = 128, BN = 128, BK = 32;
constexpr int STAGES = 3;
constexpr int A_BYTES = BM * 128;                 // 16 KB / stage
constexpr int B_BYTES = BN * 128;                 // 16 KB / stage
constexpr int STAGE_BYTES = A_BYTES + B_BYTES;    // 32 KB
constexpr int SMEM_BYTES  = STAGES * STAGE_BYTES; // 96 KB (x2 CTAs = 192 KB/SM)

// C[M,N] = A[M,K] @ B[N,K]^T (+bias, optional GELU+rna). A row-major, B n-major, tf32 pre-rounded.
template <int KD, bool DO_GELU>
__global__ __launch_bounds__(256, 2)
void gemm_tf32_v6(const float* __restrict__ A,
                  const float* __restrict__ B,     // [N][KD] n-major
                  const float* __restrict__ bias,
                  float* __restrict__ C,
                  int ldn,
                  size_t batchA, size_t batchB, size_t batchC)
{
    extern __shared__ char smem[];
    uint32_t sbase;
    asm("{ .reg .u64 t; cvta.to.shared.u64 t, %1; cvt.u32.u64 %0, t; }" : "=r"(sbase) : "l"(smem));

    const int tid  = threadIdx.x;
    const int warp = tid >> 5;
    const int lane = tid & 31;
    const int wm = warp & 3;             // 4 warps along M (32 rows each)
    const int wn = warp >> 2;            // 2 warps along N (64 cols each)
    const int m0 = wm * 32;
    const int n0 = wn * 64;
    const int r  = lane >> 2;
    const int c  = lane & 3;
    const int l8    = lane & 7;
    const int l16   = lane & 15;
    const int l8sel = (lane >> 3) & 1;
    const int lhi16 = lane >> 4;

    const float* Ab = A + (size_t)blockIdx.z * batchA + (size_t)(blockIdx.y * BM) * KD;
    const float* Bb = B + (size_t)blockIdx.z * batchB + (size_t)(blockIdx.x * BN) * KD;

    auto load_tile = [&](int kt, int s) {
        const uint32_t stage = sbase + s * STAGE_BYTES;
        #pragma unroll
        for (int i = 0; i < 4; i++) {
            int row   = (tid >> 3) + i * 32;
            int col16 = tid & 7;
            uint32_t dst = stage + row * 128 + ((col16 ^ (row & 7)) << 4);
            const float* g = Ab + (size_t)row * KD + kt * BK + col16 * 4;
            asm volatile("cp.async.cg.shared.global [%0], [%1], 16;" :: "r"(dst), "l"(g));
        }
        #pragma unroll
        for (int i = 0; i < 4; i++) {
            int row   = (tid >> 3) + i * 32;
            int col16 = tid & 7;
            uint32_t dst = stage + A_BYTES + row * 128 + ((col16 ^ (row & 7)) << 4);
            const float* g = Bb + (size_t)row * KD + kt * BK + col16 * 4;
            asm volatile("cp.async.cg.shared.global [%0], [%1], 16;" :: "r"(dst), "l"(g));
        }
        asm volatile("cp.async.commit_group;");
    };

    // Per-thread ldmatrix offsets (bytes), stage-relative; swizzle granules hoisted.
    uint32_t aRow[2], bRow[4];
    #pragma unroll
    for (int im = 0; im < 2; im++) aRow[im] = (uint32_t)(m0 + im * 16 + l16) * 128;
    #pragma unroll
    for (int p = 0; p < 4; p++)  bRow[p]  = (uint32_t)(n0 + p * 16 + lhi16 * 8 + l8) * 128;
    uint32_t gA[4], gB[4];
    #pragma unroll
    for (int k = 0; k < 4; k++) {
        gA[k] = (uint32_t)(((2 * k + lhi16) ^ l8) << 4);
        gB[k] = (uint32_t)(((2 * k + l8sel) ^ l8) << 4);
    }

    float acc[2][8][4];
    #pragma unroll
    for (int im = 0; im < 2; im++)
        #pragma unroll
        for (int in = 0; in < 8; in++)
            #pragma unroll
            for (int q = 0; q < 4; q++)
                acc[im][in][q] = 0.0f;

    constexpr int NT = KD / BK;
    load_tile(0, 0);
    load_tile(1, 1);

    int stage_c = 0;   // stage holding tile t
    for (int t = 0; t < NT; ++t) {
        if (t + 1 < NT) {
            asm volatile("cp.async.wait_group 1;");   // tile t resident (t+1 may pend)
        } else {
            asm volatile("cp.async.wait_group 0;");
        }
        __syncthreads();   // tile t visible; stage (t+2)%3 fully consumed by compute(t-1)

        // Issue next-next tile FIRST: gives the fetch a full tile of latency slack.
        if (t + 2 < NT) {
            int s = stage_c + 2; if (s >= STAGES) s -= STAGES;   // (t+2) % 3
            load_tile(t + 2, s);
        }

        const uint32_t aBase = sbase + stage_c * STAGE_BYTES;
        const uint32_t bBase = aBase + A_BYTES;

        #pragma unroll
        for (int kki = 0; kki < 4; kki++) {
            uint32_t af[2][4];
            #pragma unroll
            for (int im = 0; im < 2; im++) {
                uint32_t addr = aBase + aRow[im] + gA[kki];
                LDSM_X4(af[im][0], af[im][1], af[im][2], af[im][3], addr);
            }
            uint32_t bf[8][2];
            #pragma unroll
            for (int p = 0; p < 4; p++) {
                uint32_t addr = bBase + bRow[p] + gB[kki];
                LDSM_X4(bf[2 * p][0], bf[2 * p][1], bf[2 * p + 1][0], bf[2 * p + 1][1], addr);
            }
            #pragma unroll
            for (int im = 0; im < 2; im++)
                #pragma unroll
                for (int in = 0; in < 8; in++) {
                    float* cc = acc[im][in];
                    asm volatile(
                        "mma.sync.aligned.m16n8k8.row.col.f32.tf32.tf32.f32 "
                        "{%0,%1,%2,%3},{%4,%5,%6,%7},{%8,%9},{%0,%1,%2,%3};"
                        : "+f"(cc[0]), "+f"(cc[1]), "+f"(cc[2]), "+f"(cc[3])
                        : "r"(af[im][0]), "r"(af[im][1]), "r"(af[im][2]), "r"(af[im][3]),
                          "r"(bf[in][0]), "r"(bf[in][1]));
                }
        }

        if (++stage_c == STAGES) stage_c = 0;
    }

    // Epilogue: bias (+GELU, rna-rounded so GEMM2's A needs no cvt)
    float* Cb = C + (size_t)blockIdx.z * batchC;
    #pragma unroll
    for (int im = 0; im < 2; im++) {
        #pragma unroll
        for (int in = 0; in < 8; in++) {
            int grow = blockIdx.y * BM + m0 + im * 16 + r;
            int gcol = blockIdx.x * BN + n0 + in * 8 + c * 2;
            float bv0 = bias[gcol];
            float bv1 = bias[gcol + 1];
            float v0 = acc[im][in][0] + bv0;
            float v1 = acc[im][in][1] + bv1;
            float v2 = acc[im][in][2] + bv0;
            float v3 = acc[im][in][3] + bv1;
            if (DO_GELU) {
                v0 = rnaf(gelu_exact(v0)); v1 = rnaf(gelu_exact(v1));
                v2 = rnaf(gelu_exact(v2)); v3 = rnaf(gelu_exact(v3));
            }
            *(float2*)(Cb + (size_t)grow * ldn + gcol)       = make_float2(v0, v1);
            *(float2*)(Cb + (size_t)(grow + 8) * ldn + gcol) = make_float2(v2, v3);
        }
    }
}

// ===================== Pre-pass kernels =====================
__global__ void convert_rna_kernel(const float* __restrict__ in, float* __restrict__ out, size_t n4) {
    size_t i = (size_t)blockIdx.x * blockDim.x + threadIdx.x;
    if (i < n4) {
        float4 v = ((const float4*)in)[i];
        v.x = rnaf(v.x); v.y = rnaf(v.y); v.z = rnaf(v.z); v.w = rnaf(v.w);
        ((float4*)out)[i] = v;
    }
}

// out[e][cI][rI] = rna(in[e][rI][cI]); grid (C/32, R/32, E), block (32,8)
__global__ void transpose_cvt_kernel(const float* __restrict__ in, float* __restrict__ out, int R, int C) {
    __shared__ float tile[32][33];
    const int e  = blockIdx.z;
    const int r0 = blockIdx.y * 32;
    const int c0 = blockIdx.x * 32;
    const float* ine  = in  + (size_t)e * R * C;
    float*       oute = out + (size_t)e * R * C;
    const int tx = threadIdx.x, ty = threadIdx.y;
    #pragma unroll
    for (int k = 0; k < 4; k++)
        tile[ty + 8 * k][tx] = ine[(size_t)(r0 + ty + 8 * k) * C + c0 + tx];
    __syncthreads();
    #pragma unroll
    for (int k = 0; k < 4; k++)
        oute[(size_t)(c0 + ty + 8 * k) * R + r0 + tx] = rnaf(tile[tx][ty + 8 * k]);
}

extern "C" void kernel_launch(void* const* d_in, const int* in_sizes, int n_in,
                              void* d_out, int out_size)
{
    const float* x  = (const float*)d_in[0];
    const float* w1 = (const float*)d_in[1];
    const float* w2 = (const float*)d_in[2];
    const float* b1 = (const float*)d_in[3];
    const float* b2 = (const float*)d_in[4];
    float* out = (float*)d_out;

    float *hidden, *xc, *w1t, *w2t;
    cudaGetSymbolAddress((void**)&hidden, g_hidden);
    cudaGetSymbolAddress((void**)&xc,  g_xc);
    cudaGetSymbolAddress((void**)&w1t, g_w1t);
    cudaGetSymbolAddress((void**)&w2t, g_w2t);

    // Static side-stream + events for capture fork/join (host resources, no device allocs)
    static cudaStream_t s2 = nullptr;
    static cudaEvent_t evFork = nullptr, evJoin = nullptr;
    if (!s2) {
        cudaStreamCreateWithFlags(&s2, cudaStreamNonBlocking);
        cudaEventCreateWithFlags(&evFork, cudaEventDisableTiming);
        cudaEventCreateWithFlags(&evJoin, cudaEventDisableTiming);
    }

    dim3 tb(32, 8);

    // Fork: w2 transpose (only needed by GEMM2) runs concurrent with x/w1 prepass + GEMM1
    cudaEventRecord(evFork, 0);
    cudaStreamWaitEvent(s2, evFork, 0);
    transpose_cvt_kernel<<<dim3(DDIM / 32, HDIM / 32, NE), tb, 0, s2>>>(w2, w2t, HDIM, DDIM);
    cudaEventRecord(evJoin, s2);

    // Main stream: x convert + w1 transpose -> GEMM1
    {
        size_t nx = (size_t)NE * NTOK * DDIM / 4;
        convert_rna_kernel<<<(unsigned)((nx + 255) / 256), 256>>>(x, xc, nx);
        transpose_cvt_kernel<<<dim3(HDIM / 32, DDIM / 32, NE), tb>>>(w1, w1t, DDIM, HDIM);
    }

    cudaFuncSetAttribute(gemm_tf32_v6<DDIM, true>,
                         cudaFuncAttributeMaxDynamicSharedMemorySize, SMEM_BYTES);
    cudaFuncSetAttribute(gemm_tf32_v6<HDIM, false>,
                         cudaFuncAttributeMaxDynamicSharedMemorySize, SMEM_BYTES);

    // GEMM1: hidden = rna(GELU(x @ w1 + b1))   per expert (2048x1024)@(1024x4096)
    dim3 g1(HDIM / BN, NTOK / BM, NE);
    gemm_tf32_v6<DDIM, true><<<g1, 256, SMEM_BYTES>>>(
        xc, w1t, b1, hidden, HDIM,
        (size_t)NTOK * DDIM, (size_t)DDIM * HDIM, (size_t)NTOK * HDIM);

    // Join: GEMM2 needs w2t
    cudaStreamWaitEvent(0, evJoin, 0);

    // GEMM2: out = hidden @ w2 + b2            per expert (2048x4096)@(4096x1024)
    dim3 g2(DDIM / BN, NTOK / BM, NE);
    gemm_tf32_v6<HDIM, false><<<g2, 256, SMEM_BYTES>>>(
        hidden, w2t, b2, out, DDIM,
        (size_t)NTOK * HDIM, (size_t)HDIM * DDIM, (size_t)NTOK * DDIM);
}

// round 12
// speedup vs baseline: 1.0301x; 1.0301x over previous
#include <cuda_runtime.h>
#include <cstdint>
#include <math.h>

// Problem dims
#define NE    16
#define NTOK  2048
#define DDIM  1024
#define HDIM  4096

// Static scratch (no allocs allowed)
__device__ float g_hidden[(size_t)NE * NTOK * HDIM];   // GEMM1 out (tf32-rounded values)
__device__ float g_xc [(size_t)NE * NTOK * DDIM];      // x  pre-rounded to tf32 (row-major)
__device__ float g_w1t[(size_t)NE * DDIM * HDIM];      // w1 -> [E,H,D] (n-major), tf32-rounded
__device__ float g_w2t[(size_t)NE * DDIM * HDIM];      // w2 -> [E,D,H] (n-major), tf32-rounded

__device__ __forceinline__ float rnaf(float x) {
    uint32_t r; asm("cvt.rna.tf32.f32 %0, %1;" : "=r"(r) : "f"(x));
    return __uint_as_float(r);
}
__device__ __forceinline__ float gelu_exact(float x) {
    return 0.5f * x * (1.0f + erff(x * 0.7071067811865476f));
}

#define LDSM_X4(d0, d1, d2, d3, addr) \
    asm volatile("ldmatrix.sync.aligned.m8n8.x4.shared.b16 {%0,%1,%2,%3}, [%4];" \
        : "=r"(d0), "=r"(d1), "=r"(d2), "=r"(d3) : "r"(addr))

// ===================== GEMM config =====================
// Block tile 128(M) x 128(N) x 32(K); 128 threads (4 warps), warp tile 64x64; 3 CTAs/SM.
// 2-stage cp.async double buffer; one __syncthreads per tile.
// Arithmetic intensity: A+B each read 2x per tile -> 8 MAC/smem-byte (vs 5.3 before).
// Tiles stored as [rows][32 tf32 = 128B] with 16B-granule swizzle: granule' = granule ^ (row % 8)
constexpr int BM = 128, BN = 128, BK = 32;
constexpr int STAGES = 2;
constexpr int A_BYTES = BM * 128;                 // 16 KB / stage
constexpr int B_BYTES = BN * 128;                 // 16 KB / stage
constexpr int STAGE_BYTES = A_BYTES + B_BYTES;    // 32 KB
constexpr int SMEM_BYTES  = STAGES * STAGE_BYTES; // 64 KB (x3 CTAs = 192 KB/SM)

// C[M,N] = A[M,K] @ B[N,K]^T (+bias, optional GELU+rna). A row-major, B n-major, tf32 pre-rounded.
template <int KD, bool DO_GELU>
__global__ __launch_bounds__(128, 3)
void gemm_tf32_v7(const float* __restrict__ A,
                  const float* __restrict__ B,     // [N][KD] n-major
                  const float* __restrict__ bias,
                  float* __restrict__ C,
                  int ldn,
                  size_t batchA, size_t batchB, size_t batchC)
{
    extern __shared__ char smem[];
    uint32_t sbase;
    asm("{ .reg .u64 t; cvta.to.shared.u64 t, %1; cvt.u32.u64 %0, t; }" : "=r"(sbase) : "l"(smem));

    const int tid  = threadIdx.x;
    const int warp = tid >> 5;
    const int lane = tid & 31;
    const int wm = warp & 1;             // 2 warps along M (64 rows each)
    const int wn = warp >> 1;            // 2 warps along N (64 cols each)
    const int m0 = wm * 64;
    const int n0 = wn * 64;
    const int r  = lane >> 2;
    const int c  = lane & 3;
    const int l8    = lane & 7;
    const int l16   = lane & 15;
    const int l8sel = (lane >> 3) & 1;
    const int lhi16 = lane >> 4;

    const float* Ab = A + (size_t)blockIdx.z * batchA + (size_t)(blockIdx.y * BM) * KD;
    const float* Bb = B + (size_t)blockIdx.z * batchB + (size_t)(blockIdx.x * BN) * KD;

    auto load_tile = [&](int kt, int s) {
        const uint32_t stage = sbase + s * STAGE_BYTES;
        // A: 128 rows x 128B (8 cp.async per thread @128 threads)
        #pragma unroll
        for (int i = 0; i < 8; i++) {
            int row   = (tid >> 3) + i * 16;
            int col16 = tid & 7;
            uint32_t dst = stage + row * 128 + ((col16 ^ (row & 7)) << 4);
            const float* g = Ab + (size_t)row * KD + kt * BK + col16 * 4;
            asm volatile("cp.async.cg.shared.global [%0], [%1], 16;" :: "r"(dst), "l"(g));
        }
        // B: 128 rows x 128B
        #pragma unroll
        for (int i = 0; i < 8; i++) {
            int row   = (tid >> 3) + i * 16;
            int col16 = tid & 7;
            uint32_t dst = stage + A_BYTES + row * 128 + ((col16 ^ (row & 7)) << 4);
            const float* g = Bb + (size_t)row * KD + kt * BK + col16 * 4;
            asm volatile("cp.async.cg.shared.global [%0], [%1], 16;" :: "r"(dst), "l"(g));
        }
        asm volatile("cp.async.commit_group;");
    };

    // Per-thread ldmatrix row offsets (bytes), stage-relative
    uint32_t aRow[4], bRow[4];
    #pragma unroll
    for (int im = 0; im < 4; im++) aRow[im] = (uint32_t)(m0 + im * 16 + l16) * 128;
    #pragma unroll
    for (int p = 0; p < 4; p++)  bRow[p]  = (uint32_t)(n0 + p * 16 + lhi16 * 8 + l8) * 128;

    float acc[4][8][4];
    #pragma unroll
    for (int im = 0; im < 4; im++)
        #pragma unroll
        for (int in = 0; in < 8; in++)
            #pragma unroll
            for (int q = 0; q < 4; q++)
                acc[im][in][q] = 0.0f;

    constexpr int NT = KD / BK;
    load_tile(0, 0);

    for (int t = 0; t < NT; ++t) {
        asm volatile("cp.async.wait_group 0;");   // tile t resident
        __syncthreads();                           // visible to all; prev-stage reads done

        // Prefetch next tile into the other stage; overlaps with compute below.
        if (t + 1 < NT) load_tile(t + 1, (t + 1) & 1);

        const uint32_t aBase = sbase + (t & 1) * STAGE_BYTES;
        const uint32_t bBase = aBase + A_BYTES;

        #pragma unroll
        for (int kki = 0; kki < 4; kki++) {
            const uint32_t gAk = (uint32_t)(((2 * kki + lhi16) ^ l8) << 4);
            const uint32_t gBk = (uint32_t)(((2 * kki + l8sel) ^ l8) << 4);
            uint32_t af[4][4];
            #pragma unroll
            for (int im = 0; im < 4; im++)
                LDSM_X4(af[im][0], af[im][1], af[im][2], af[im][3], aBase + aRow[im] + gAk);
            // Process N in two 32-col halves to halve live B-frag registers
            #pragma unroll
            for (int h = 0; h < 2; h++) {
                uint32_t bf[4][2];
                #pragma unroll
                for (int p = 0; p < 2; p++) {
                    int pp = h * 2 + p;
                    LDSM_X4(bf[2 * p][0], bf[2 * p][1], bf[2 * p + 1][0], bf[2 * p + 1][1],
                            bBase + bRow[pp] + gBk);
                }
                #pragma unroll
                for (int im = 0; im < 4; im++)
                    #pragma unroll
                    for (int in = 0; in < 4; in++) {
                        float* cc = acc[im][h * 4 + in];
                        asm volatile(
                            "mma.sync.aligned.m16n8k8.row.col.f32.tf32.tf32.f32 "
                            "{%0,%1,%2,%3},{%4,%5,%6,%7},{%8,%9},{%0,%1,%2,%3};"
                            : "+f"(cc[0]), "+f"(cc[1]), "+f"(cc[2]), "+f"(cc[3])
                            : "r"(af[im][0]), "r"(af[im][1]), "r"(af[im][2]), "r"(af[im][3]),
                              "r"(bf[in][0]), "r"(bf[in][1]));
                    }
            }
        }
    }

    // Epilogue: bias (+GELU, rna-rounded so GEMM2's A needs no cvt)
    float* Cb = C + (size_t)blockIdx.z * batchC;
    #pragma unroll
    for (int im = 0; im < 4; im++) {
        #pragma unroll
        for (int in = 0; in < 8; in++) {
            int grow = blockIdx.y * BM + m0 + im * 16 + r;
            int gcol = blockIdx.x * BN + n0 + in * 8 + c * 2;
            float bv0 = bias[gcol];
            float bv1 = bias[gcol + 1];
            float v0 = acc[im][in][0] + bv0;
            float v1 = acc[im][in][1] + bv1;
            float v2 = acc[im][in][2] + bv0;
            float v3 = acc[im][in][3] + bv1;
            if (DO_GELU) {
                v0 = rnaf(gelu_exact(v0)); v1 = rnaf(gelu_exact(v1));
                v2 = rnaf(gelu_exact(v2)); v3 = rnaf(gelu_exact(v3));
            }
            *(float2*)(Cb + (size_t)grow * ldn + gcol)       = make_float2(v0, v1);
            *(float2*)(Cb + (size_t)(grow + 8) * ldn + gcol) = make_float2(v2, v3);
        }
    }
}

// ===================== Pre-pass kernels =====================
__global__ void convert_rna_kernel(const float* __restrict__ in, float* __restrict__ out, size_t n4) {
    size_t i = (size_t)blockIdx.x * blockDim.x + threadIdx.x;
    if (i < n4) {
        float4 v = ((const float4*)in)[i];
        v.x = rnaf(v.x); v.y = rnaf(v.y); v.z = rnaf(v.z); v.w = rnaf(v.w);
        ((float4*)out)[i] = v;
    }
}

// out[e][cI][rI] = rna(in[e][rI][cI]); grid (C/32, R/32, E), block (32,8)
__global__ void transpose_cvt_kernel(const float* __restrict__ in, float* __restrict__ out, int R, int C) {
    __shared__ float tile[32][33];
    const int e  = blockIdx.z;
    const int r0 = blockIdx.y * 32;
    const int c0 = blockIdx.x * 32;
    const float* ine  = in  + (size_t)e * R * C;
    float*       oute = out + (size_t)e * R * C;
    const int tx = threadIdx.x, ty = threadIdx.y;
    #pragma unroll
    for (int k = 0; k < 4; k++)
        tile[ty + 8 * k][tx] = ine[(size_t)(r0 + ty + 8 * k) * C + c0 + tx];
    __syncthreads();
    #pragma unroll
    for (int k = 0; k < 4; k++)
        oute[(size_t)(c0 + ty + 8 * k) * R + r0 + tx] = rnaf(tile[tx][ty + 8 * k]);
}

extern "C" void kernel_launch(void* const* d_in, const int* in_sizes, int n_in,
                              void* d_out, int out_size)
{
    const float* x  = (const float*)d_in[0];
    const float* w1 = (const float*)d_in[1];
    const float* w2 = (const float*)d_in[2];
    const float* b1 = (const float*)d_in[3];
    const float* b2 = (const float*)d_in[4];
    float* out = (float*)d_out;

    float *hidden, *xc, *w1t, *w2t;
    cudaGetSymbolAddress((void**)&hidden, g_hidden);
    cudaGetSymbolAddress((void**)&xc,  g_xc);
    cudaGetSymbolAddress((void**)&w1t, g_w1t);
    cudaGetSymbolAddress((void**)&w2t, g_w2t);

    // Pre-pass: rna-round x; transpose+round w1 -> [E,H,D], w2 -> [E,D,H]
    {
        size_t nx = (size_t)NE * NTOK * DDIM / 4;
        convert_rna_kernel<<<(unsigned)((nx + 255) / 256), 256>>>(x, xc, nx);
        dim3 tb(32, 8);
        transpose_cvt_kernel<<<dim3(HDIM / 32, DDIM / 32, NE), tb>>>(w1, w1t, DDIM, HDIM);
        transpose_cvt_kernel<<<dim3(DDIM / 32, HDIM / 32, NE), tb>>>(w2, w2t, HDIM, DDIM);
    }

    cudaFuncSetAttribute(gemm_tf32_v7<DDIM, true>,
                         cudaFuncAttributeMaxDynamicSharedMemorySize, SMEM_BYTES);
    cudaFuncSetAttribute(gemm_tf32_v7<HDIM, false>,
                         cudaFuncAttributeMaxDynamicSharedMemorySize, SMEM_BYTES);

    // GEMM1: hidden = rna(GELU(x @ w1 + b1))   per expert (2048x1024)@(1024x4096)
    dim3 g1(HDIM / BN, NTOK / BM, NE);
    gemm_tf32_v7<DDIM, true><<<g1, 128, SMEM_BYTES>>>(
        xc, w1t, b1, hidden, HDIM,
        (size_t)NTOK * DDIM, (size_t)DDIM * HDIM, (size_t)NTOK * HDIM);

    // GEMM2: out = hidden @ w2 + b2            per expert (2048x4096)@(4096x1024)
    dim3 g2(DDIM / BN, NTOK / BM, NE);
    gemm_tf32_v7<HDIM, false><<<g2, 128, SMEM_BYTES>>>(
        hidden, w2t, b2, out, DDIM,
        (size_t)NTOK * HDIM, (size_t)HDIM * DDIM, (size_t)NTOK * DDIM);
}

// round 13
// speedup vs baseline: 1.0541x; 1.0233x over previous
#include <cuda_runtime.h>
#include <cstdint>
#include <math.h>

// Problem dims
#define NE    16
#define NTOK  2048
#define DDIM  1024
#define HDIM  4096

// Static scratch (no allocs allowed)
__device__ float g_hidden[(size_t)NE * NTOK * HDIM];   // GEMM1 out (tf32-rounded values)
__device__ float g_xc [(size_t)NE * NTOK * DDIM];      // x  pre-rounded to tf32 (row-major)
__device__ float g_w1t[(size_t)NE * DDIM * HDIM];      // w1 -> [E,H,D] (n-major), tf32-rounded
__device__ float g_w2t[(size_t)NE * DDIM * HDIM];      // w2 -> [E,D,H] (n-major), tf32-rounded

__device__ __forceinline__ float rnaf(float x) {
    uint32_t r; asm("cvt.rna.tf32.f32 %0, %1;" : "=r"(r) : "f"(x));
    return __uint_as_float(r);
}
__device__ __forceinline__ float gelu_exact(float x) {
    return 0.5f * x * (1.0f + erff(x * 0.7071067811865476f));
}

#define LDSM_X4(d0, d1, d2, d3, addr) \
    asm volatile("ldmatrix.sync.aligned.m8n8.x4.shared.b16 {%0,%1,%2,%3}, [%4];" \
        : "=r"(d0), "=r"(d1), "=r"(d2), "=r"(d3) : "r"(addr))

// ===================== GEMM config =====================
// Block tile 128(M) x 128(N) x 32(K); 128 threads (4 warps), warp tile 64x64; 3 CTAs/SM.
// 2-stage cp.async double buffer, one barrier/tile; prefetch spread across the kki loop.
// Tiles stored as [rows][32 tf32 = 128B] with 16B-granule swizzle: granule' = granule ^ (row % 8)
constexpr int BM = 128, BN = 128, BK = 32;
constexpr int STAGES = 2;
constexpr int A_BYTES = BM * 128;                 // 16 KB / stage
constexpr int B_BYTES = BN * 128;                 // 16 KB / stage
constexpr int STAGE_BYTES = A_BYTES + B_BYTES;    // 32 KB
constexpr int SMEM_BYTES  = STAGES * STAGE_BYTES; // 64 KB (x3 CTAs = 192 KB/SM)

// C[M,N] = A[M,K] @ B[N,K]^T (+bias, optional GELU+rna). A row-major, B n-major, tf32 pre-rounded.
template <int KD, bool DO_GELU>
__global__ __launch_bounds__(128, 3)
void gemm_tf32_v8(const float* __restrict__ A,
                  const float* __restrict__ B,     // [N][KD] n-major
                  const float* __restrict__ bias,
                  float* __restrict__ C,
                  int ldn,
                  size_t batchA, size_t batchB, size_t batchC)
{
    extern __shared__ char smem[];
    uint32_t sbase;
    asm("{ .reg .u64 t; cvta.to.shared.u64 t, %1; cvt.u32.u64 %0, t; }" : "=r"(sbase) : "l"(smem));

    const int tid  = threadIdx.x;
    const int warp = tid >> 5;
    const int lane = tid & 31;
    const int wm = warp & 1;             // 2 warps along M (64 rows each)
    const int wn = warp >> 1;            // 2 warps along N (64 cols each)
    const int m0 = wm * 64;
    const int n0 = wn * 64;
    const int r  = lane >> 2;
    const int c  = lane & 3;
    const int l8    = lane & 7;
    const int l16   = lane & 15;
    const int l8sel = (lane >> 3) & 1;
    const int lhi16 = lane >> 4;

    // Per-thread load lane: row0 = tid>>3 (i-th load adds 16 rows), col16 = tid&7
    const int row0  = tid >> 3;
    const int col16 = tid & 7;
    const uint32_t smOff = (uint32_t)(row0 * 128 + ((col16 ^ (row0 & 7)) << 4));

    // Gmem pointers advance by BK floats per tile (A and B are both K-major)
    const float* aG = A + (size_t)blockIdx.z * batchA + (size_t)(blockIdx.y * BM + row0) * KD + col16 * 4;
    const float* bG = B + (size_t)blockIdx.z * batchB + (size_t)(blockIdx.x * BN + row0) * KD + col16 * 4;

    // chunk 0/1: A halves; chunk 2/3: B halves; commit on chunk 3.
    auto load_chunk = [&](const float* ag, const float* bg, uint32_t smA, int chunk) {
        if (chunk < 2) {
            #pragma unroll
            for (int j = 0; j < 4; j++) {
                const int i = chunk * 4 + j;
                asm volatile("cp.async.cg.shared.global [%0], [%1], 16;"
                    :: "r"(smA + i * 2048), "l"(ag + (size_t)i * 16 * KD));
            }
        } else {
            #pragma unroll
            for (int j = 0; j < 4; j++) {
                const int i = (chunk - 2) * 4 + j;
                asm volatile("cp.async.cg.shared.global [%0], [%1], 16;"
                    :: "r"(smA + A_BYTES + i * 2048), "l"(bg + (size_t)i * 16 * KD));
            }
            if (chunk == 3)
                asm volatile("cp.async.commit_group;");
        }
    };

    // Per-thread ldmatrix row offsets (bytes), stage-relative
    uint32_t aRow[4], bRow[4];
    #pragma unroll
    for (int im = 0; im < 4; im++) aRow[im] = (uint32_t)(m0 + im * 16 + l16) * 128;
    #pragma unroll
    for (int p = 0; p < 4; p++)  bRow[p]  = (uint32_t)(n0 + p * 16 + lhi16 * 8 + l8) * 128;

    float acc[4][8][4];
    #pragma unroll
    for (int im = 0; im < 4; im++)
        #pragma unroll
        for (int in = 0; in < 8; in++)
            #pragma unroll
            for (int q = 0; q < 4; q++)
                acc[im][in][q] = 0.0f;

    constexpr int NT = KD / BK;

    // Prologue: full tile 0 load
    {
        const uint32_t smA = sbase + smOff;
        load_chunk(aG, bG, smA, 0);
        load_chunk(aG, bG, smA, 1);
        load_chunk(aG, bG, smA, 2);
        load_chunk(aG, bG, smA, 3);
        aG += BK; bG += BK;
    }

    for (int t = 0; t < NT; ++t) {
        asm volatile("cp.async.wait_group 0;");
        __syncthreads();

        const bool pf = (t + 1 < NT);
        const uint32_t aBase = sbase + (t & 1) * STAGE_BYTES;
        const uint32_t bBase = aBase + A_BYTES;
        const uint32_t nSm   = sbase + ((t + 1) & 1) * STAGE_BYTES + smOff;

        #pragma unroll
        for (int kki = 0; kki < 4; kki++) {
            if (pf) load_chunk(aG, bG, nSm, kki);   // spread prefetch: 4 LDGSTS per kki

            const uint32_t gAk = (uint32_t)(((2 * kki + lhi16) ^ l8) << 4);
            const uint32_t gBk = (uint32_t)(((2 * kki + l8sel) ^ l8) << 4);
            uint32_t af[4][4];
            #pragma unroll
            for (int im = 0; im < 4; im++)
                LDSM_X4(af[im][0], af[im][1], af[im][2], af[im][3], aBase + aRow[im] + gAk);
            #pragma unroll
            for (int h = 0; h < 2; h++) {
                uint32_t bf[4][2];
                #pragma unroll
                for (int p = 0; p < 2; p++) {
                    int pp = h * 2 + p;
                    LDSM_X4(bf[2 * p][0], bf[2 * p][1], bf[2 * p + 1][0], bf[2 * p + 1][1],
                            bBase + bRow[pp] + gBk);
                }
                #pragma unroll
                for (int im = 0; im < 4; im++)
                    #pragma unroll
                    for (int in = 0; in < 4; in++) {
                        float* cc = acc[im][h * 4 + in];
                        asm volatile(
                            "mma.sync.aligned.m16n8k8.row.col.f32.tf32.tf32.f32 "
                            "{%0,%1,%2,%3},{%4,%5,%6,%7},{%8,%9},{%0,%1,%2,%3};"
                            : "+f"(cc[0]), "+f"(cc[1]), "+f"(cc[2]), "+f"(cc[3])
                            : "r"(af[im][0]), "r"(af[im][1]), "r"(af[im][2]), "r"(af[im][3]),
                              "r"(bf[in][0]), "r"(bf[in][1]));
                    }
            }
        }
        if (pf) { aG += BK; bG += BK; }
    }

    // Epilogue: bias (+GELU, rna-rounded so GEMM2's A needs no cvt)
    float* Cb = C + (size_t)blockIdx.z * batchC;
    #pragma unroll
    for (int im = 0; im < 4; im++) {
        #pragma unroll
        for (int in = 0; in < 8; in++) {
            int grow = blockIdx.y * BM + m0 + im * 16 + r;
            int gcol = blockIdx.x * BN + n0 + in * 8 + c * 2;
            float bv0 = bias[gcol];
            float bv1 = bias[gcol + 1];
            float v0 = acc[im][in][0] + bv0;
            float v1 = acc[im][in][1] + bv1;
            float v2 = acc[im][in][2] + bv0;
            float v3 = acc[im][in][3] + bv1;
            if (DO_GELU) {
                v0 = rnaf(gelu_exact(v0)); v1 = rnaf(gelu_exact(v1));
                v2 = rnaf(gelu_exact(v2)); v3 = rnaf(gelu_exact(v3));
            }
            *(float2*)(Cb + (size_t)grow * ldn + gcol)       = make_float2(v0, v1);
            *(float2*)(Cb + (size_t)(grow + 8) * ldn + gcol) = make_float2(v2, v3);
        }
    }
}

// ===================== Pre-pass kernels =====================
__global__ void convert_rna_kernel(const float* __restrict__ in, float* __restrict__ out, size_t n4) {
    size_t i = (size_t)blockIdx.x * blockDim.x + threadIdx.x;
    if (i < n4) {
        float4 v = ((const float4*)in)[i];
        v.x = rnaf(v.x); v.y = rnaf(v.y); v.z = rnaf(v.z); v.w = rnaf(v.w);
        ((float4*)out)[i] = v;
    }
}

// out[e][cI][rI] = rna(in[e][rI][cI]); grid (C/32, R/32, E), block (32,8)
__global__ void transpose_cvt_kernel(const float* __restrict__ in, float* __restrict__ out, int R, int C) {
    __shared__ float tile[32][33];
    const int e  = blockIdx.z;
    const int r0 = blockIdx.y * 32;
    const int c0 = blockIdx.x * 32;
    const float* ine  = in  + (size_t)e * R * C;
    float*       oute = out + (size_t)e * R * C;
    const int tx = threadIdx.x, ty = threadIdx.y;
    #pragma unroll
    for (int k = 0; k < 4; k++)
        tile[ty + 8 * k][tx] = ine[(size_t)(r0 + ty + 8 * k) * C + c0 + tx];
    __syncthreads();
    #pragma unroll
    for (int k = 0; k < 4; k++)
        oute[(size_t)(c0 + ty + 8 * k) * R + r0 + tx] = rnaf(tile[tx][ty + 8 * k]);
}

extern "C" void kernel_launch(void* const* d_in, const int* in_sizes, int n_in,
                              void* d_out, int out_size)
{
    const float* x  = (const float*)d_in[0];
    const float* w1 = (const float*)d_in[1];
    const float* w2 = (const float*)d_in[2];
    const float* b1 = (const float*)d_in[3];
    const float* b2 = (const float*)d_in[4];
    float* out = (float*)d_out;

    float *hidden, *xc, *w1t, *w2t;
    cudaGetSymbolAddress((void**)&hidden, g_hidden);
    cudaGetSymbolAddress((void**)&xc,  g_xc);
    cudaGetSymbolAddress((void**)&w1t, g_w1t);
    cudaGetSymbolAddress((void**)&w2t, g_w2t);

    // Pre-pass: rna-round x; transpose+round w1 -> [E,H,D], w2 -> [E,D,H]
    {
        size_t nx = (size_t)NE * NTOK * DDIM / 4;
        convert_rna_kernel<<<(unsigned)((nx + 255) / 256), 256>>>(x, xc, nx);
        dim3 tb(32, 8);
        transpose_cvt_kernel<<<dim3(HDIM / 32, DDIM / 32, NE), tb>>>(w1, w1t, DDIM, HDIM);
        transpose_cvt_kernel<<<dim3(DDIM / 32, HDIM / 32, NE), tb>>>(w2, w2t, HDIM, DDIM);
    }

    cudaFuncSetAttribute(gemm_tf32_v8<DDIM, true>,
                         cudaFuncAttributeMaxDynamicSharedMemorySize, SMEM_BYTES);
    cudaFuncSetAttribute(gemm_tf32_v8<HDIM, false>,
                         cudaFuncAttributeMaxDynamicSharedMemorySize, SMEM_BYTES);

    // GEMM1: hidden = rna(GELU(x @ w1 + b1))   per expert (2048x1024)@(1024x4096)
    dim3 g1(HDIM / BN, NTOK / BM, NE);
    gemm_tf32_v8<DDIM, true><<<g1, 128, SMEM_BYTES>>>(
        xc, w1t, b1, hidden, HDIM,
        (size_t)NTOK * DDIM, (size_t)DDIM * HDIM, (size_t)NTOK * HDIM);

    // GEMM2: out = hidden @ w2 + b2            per expert (2048x4096)@(4096x1024)
    dim3 g2(DDIM / BN, NTOK / BM, NE);
    gemm_tf32_v8<HDIM, false><<<g2, 128, SMEM_BYTES>>>(
        hidden, w2t, b2, out, DDIM,
        (size_t)NTOK * HDIM, (size_t)HDIM * DDIM, (size_t)NTOK * DDIM);
}

// round 16
// speedup vs baseline: 1.0697x; 1.0148x over previous
#include <cuda_runtime.h>
#include <cstdint>
#include <math.h>

// Problem dims
#define NE    16
#define NTOK  2048
#define DDIM  1024
#define HDIM  4096

// Static scratch (no allocs allowed)
__device__ float g_hidden[(size_t)NE * NTOK * HDIM];   // GEMM1 out (tf32-rounded values)
__device__ float g_xc [(size_t)NE * NTOK * DDIM];      // x  pre-rounded to tf32 (row-major)
__device__ float g_w1t[(size_t)NE * DDIM * HDIM];      // w1 -> [E,H,D] (n-major), tf32-rounded
__device__ float g_w2t[(size_t)NE * DDIM * HDIM];      // w2 -> [E,D,H] (n-major), tf32-rounded

__device__ __forceinline__ float rnaf(float x) {
    uint32_t r; asm("cvt.rna.tf32.f32 %0, %1;" : "=r"(r) : "f"(x));
    return __uint_as_float(r);
}
__device__ __forceinline__ float gelu_exact(float x) {
    return 0.5f * x * (1.0f + erff(x * 0.7071067811865476f));
}

#define LDSM_X4(d0, d1, d2, d3, addr) \
    asm volatile("ldmatrix.sync.aligned.m8n8.x4.shared.b16 {%0,%1,%2,%3}, [%4];" \
        : "=r"(d0), "=r"(d1), "=r"(d2), "=r"(d3) : "r"(addr))

// ===================== GEMM config =====================
// Block tile 128(M) x 128(N) x 32(K); 128 threads (4 warps), warp tile 64x64; 3 CTAs/SM.
// 2-stage cp.async double buffer, one barrier/tile.
// SPREAD=false: bulk prefetch of tile t+1 right after the barrier (best for NT=32).
// SPREAD=true : prefetch spread across the 4 kki steps (best for NT=128).
// Tiles stored as [rows][32 tf32 = 128B] with 16B-granule swizzle: granule' = granule ^ (row % 8)
constexpr int BM = 128, BN = 128, BK = 32;
constexpr int STAGES = 2;
constexpr int A_BYTES = BM * 128;                 // 16 KB / stage
constexpr int B_BYTES = BN * 128;                 // 16 KB / stage
constexpr int STAGE_BYTES = A_BYTES + B_BYTES;    // 32 KB
constexpr int SMEM_BYTES  = STAGES * STAGE_BYTES; // 64 KB (x3 CTAs = 192 KB/SM)

// C[M,N] = A[M,K] @ B[N,K]^T (+bias, optional GELU+rna). A row-major, B n-major, tf32 pre-rounded.
template <int KD, bool DO_GELU, bool SPREAD>
__global__ __launch_bounds__(128, 3)
void gemm_tf32_v9(const float* __restrict__ A,
                  const float* __restrict__ B,     // [N][KD] n-major
                  const float* __restrict__ bias,
                  float* __restrict__ C,
                  int ldn,
                  size_t batchA, size_t batchB, size_t batchC)
{
    extern __shared__ char smem[];
    uint32_t sbase;
    asm("{ .reg .u64 t; cvta.to.shared.u64 t, %1; cvt.u32.u64 %0, t; }" : "=r"(sbase) : "l"(smem));

    const int tid  = threadIdx.x;
    const int warp = tid >> 5;
    const int lane = tid & 31;
    const int wm = warp & 1;             // 2 warps along M (64 rows each)
    const int wn = warp >> 1;            // 2 warps along N (64 cols each)
    const int m0 = wm * 64;
    const int n0 = wn * 64;
    const int r  = lane >> 2;
    const int c  = lane & 3;
    const int l8    = lane & 7;
    const int l16   = lane & 15;
    const int l8sel = (lane >> 3) & 1;
    const int lhi16 = lane >> 4;

    // Per-thread load lane: row0 = tid>>3 (i-th load adds 16 rows), col16 = tid&7
    const int row0  = tid >> 3;
    const int col16 = tid & 7;
    const uint32_t smOff = (uint32_t)(row0 * 128 + ((col16 ^ (row0 & 7)) << 4));

    // Gmem pointers advance by BK floats per tile (A and B are both K-major)
    const float* aG = A + (size_t)blockIdx.z * batchA + (size_t)(blockIdx.y * BM + row0) * KD + col16 * 4;
    const float* bG = B + (size_t)blockIdx.z * batchB + (size_t)(blockIdx.x * BN + row0) * KD + col16 * 4;

    // chunk 0/1: A halves; chunk 2/3: B halves; commit on chunk 3.
    auto load_chunk = [&](const float* ag, const float* bg, uint32_t smA, int chunk) {
        if (chunk < 2) {
            #pragma unroll
            for (int j = 0; j < 4; j++) {
                const int i = chunk * 4 + j;
                asm volatile("cp.async.cg.shared.global [%0], [%1], 16;"
                    :: "r"(smA + i * 2048), "l"(ag + (size_t)i * 16 * KD));
            }
        } else {
            #pragma unroll
            for (int j = 0; j < 4; j++) {
                const int i = (chunk - 2) * 4 + j;
                asm volatile("cp.async.cg.shared.global [%0], [%1], 16;"
                    :: "r"(smA + A_BYTES + i * 2048), "l"(bg + (size_t)i * 16 * KD));
            }
            if (chunk == 3)
                asm volatile("cp.async.commit_group;");
        }
    };

    // Per-thread ldmatrix row offsets (bytes), stage-relative; swizzle granules hoisted.
    uint32_t aRow[4], bRow[4];
    #pragma unroll
    for (int im = 0; im < 4; im++) aRow[im] = (uint32_t)(m0 + im * 16 + l16) * 128;
    #pragma unroll
    for (int p = 0; p < 4; p++)  bRow[p]  = (uint32_t)(n0 + p * 16 + lhi16 * 8 + l8) * 128;
    uint32_t gA[4], gB[4];
    #pragma unroll
    for (int k = 0; k < 4; k++) {
        gA[k] = (uint32_t)(((2 * k + lhi16) ^ l8) << 4);
        gB[k] = (uint32_t)(((2 * k + l8sel) ^ l8) << 4);
    }

    float acc[4][8][4];
    #pragma unroll
    for (int im = 0; im < 4; im++)
        #pragma unroll
        for (int in = 0; in < 8; in++)
            #pragma unroll
            for (int q = 0; q < 4; q++)
                acc[im][in][q] = 0.0f;

    constexpr int NT = KD / BK;

    // Prologue: full tile 0 load
    {
        const uint32_t smA = sbase + smOff;
        load_chunk(aG, bG, smA, 0);
        load_chunk(aG, bG, smA, 1);
        load_chunk(aG, bG, smA, 2);
        load_chunk(aG, bG, smA, 3);
        aG += BK; bG += BK;
    }

    for (int t = 0; t < NT; ++t) {
        asm volatile("cp.async.wait_group 0;");
        __syncthreads();

        const bool pf = (t + 1 < NT);
        const uint32_t aBase = sbase + (t & 1) * STAGE_BYTES;
        const uint32_t bBase = aBase + A_BYTES;
        const uint32_t nSm   = sbase + ((t + 1) & 1) * STAGE_BYTES + smOff;

        if (!SPREAD && pf) {   // bulk prefetch up front (GEMM1-best schedule)
            load_chunk(aG, bG, nSm, 0);
            load_chunk(aG, bG, nSm, 1);
            load_chunk(aG, bG, nSm, 2);
            load_chunk(aG, bG, nSm, 3);
        }

        #pragma unroll
        for (int kki = 0; kki < 4; kki++) {
            if (SPREAD && pf) load_chunk(aG, bG, nSm, kki);   // spread prefetch (GEMM2-best)

            uint32_t af[4][4];
            #pragma unroll
            for (int im = 0; im < 4; im++)
                LDSM_X4(af[im][0], af[im][1], af[im][2], af[im][3], aBase + aRow[im] + gA[kki]);
            #pragma unroll
            for (int h = 0; h < 2; h++) {
                uint32_t bf[4][2];
                #pragma unroll
                for (int p = 0; p < 2; p++) {
                    int pp = h * 2 + p;
                    LDSM_X4(bf[2 * p][0], bf[2 * p][1], bf[2 * p + 1][0], bf[2 * p + 1][1],
                            bBase + bRow[pp] + gB[kki]);
                }
                #pragma unroll
                for (int im = 0; im < 4; im++)
                    #pragma unroll
                    for (int in = 0; in < 4; in++) {
                        float* cc = acc[im][h * 4 + in];
                        asm volatile(
                            "mma.sync.aligned.m16n8k8.row.col.f32.tf32.tf32.f32 "
                            "{%0,%1,%2,%3},{%4,%5,%6,%7},{%8,%9},{%0,%1,%2,%3};"
                            : "+f"(cc[0]), "+f"(cc[1]), "+f"(cc[2]), "+f"(cc[3])
                            : "r"(af[im][0]), "r"(af[im][1]), "r"(af[im][2]), "r"(af[im][3]),
                              "r"(bf[in][0]), "r"(bf[in][1]));
                    }
            }
        }
        if (pf) { aG += BK; bG += BK; }
    }

    // Epilogue: bias (+GELU, rna-rounded so GEMM2's A needs no cvt)
    float* Cb = C + (size_t)blockIdx.z * batchC;
    #pragma unroll
    for (int im = 0; im < 4; im++) {
        #pragma unroll
        for (int in = 0; in < 8; in++) {
            int grow = blockIdx.y * BM + m0 + im * 16 + r;
            int gcol = blockIdx.x * BN + n0 + in * 8 + c * 2;
            float bv0 = bias[gcol];
            float bv1 = bias[gcol + 1];
            float v0 = acc[im][in][0] + bv0;
            float v1 = acc[im][in][1] + bv1;
            float v2 = acc[im][in][2] + bv0;
            float v3 = acc[im][in][3] + bv1;
            if (DO_GELU) {
                v0 = rnaf(gelu_exact(v0)); v1 = rnaf(gelu_exact(v1));
                v2 = rnaf(gelu_exact(v2)); v3 = rnaf(gelu_exact(v3));
            }
            *(float2*)(Cb + (size_t)grow * ldn + gcol)       = make_float2(v0, v1);
            *(float2*)(Cb + (size_t)(grow + 8) * ldn + gcol) = make_float2(v2, v3);
        }
    }
}

// ===================== Pre-pass kernels =====================
__global__ void convert_rna_kernel(const float* __restrict__ in, float* __restrict__ out, size_t n4) {
    size_t i = (size_t)blockIdx.x * blockDim.x + threadIdx.x;
    if (i < n4) {
        float4 v = ((const float4*)in)[i];
        v.x = rnaf(v.x); v.y = rnaf(v.y); v.z = rnaf(v.z); v.w = rnaf(v.w);
        ((float4*)out)[i] = v;
    }
}

// out[e][cI][rI] = rna(in[e][rI][cI]); grid (C/32, R/32, E), block (32,8)
__global__ void transpose_cvt_kernel(const float* __restrict__ in, float* __restrict__ out, int R, int C) {
    __shared__ float tile[32][33];
    const int e  = blockIdx.z;
    const int r0 = blockIdx.y * 32;
    const int c0 = blockIdx.x * 32;
    const float* ine  = in  + (size_t)e * R * C;
    float*       oute = out + (size_t)e * R * C;
    const int tx = threadIdx.x, ty = threadIdx.y;
    #pragma unroll
    for (int k = 0; k < 4; k++)
        tile[ty + 8 * k][tx] = ine[(size_t)(r0 + ty + 8 * k) * C + c0 + tx];
    __syncthreads();
    #pragma unroll
    for (int k = 0; k < 4; k++)
        oute[(size_t)(c0 + ty + 8 * k) * R + r0 + tx] = rnaf(tile[tx][ty + 8 * k]);
}

extern "C" void kernel_launch(void* const* d_in, const int* in_sizes, int n_in,
                              void* d_out, int out_size)
{
    const float* x  = (const float*)d_in[0];
    const float* w1 = (const float*)d_in[1];
    const float* w2 = (const float*)d_in[2];
    const float* b1 = (const float*)d_in[3];
    const float* b2 = (const float*)d_in[4];
    float* out = (float*)d_out;

    float *hidden, *xc, *w1t, *w2t;
    cudaGetSymbolAddress((void**)&hidden, g_hidden);
    cudaGetSymbolAddress((void**)&xc,  g_xc);
    cudaGetSymbolAddress((void**)&w1t, g_w1t);
    cudaGetSymbolAddress((void**)&w2t, g_w2t);

    // Pre-pass: rna-round x; transpose+round w1 -> [E,H,D], w2 -> [E,D,H]
    {
        size_t nx = (size_t)NE * NTOK * DDIM / 4;
        convert_rna_kernel<<<(unsigned)((nx + 255) / 256), 256>>>(x, xc, nx);
        dim3 tb(32, 8);
        transpose_cvt_kernel<<<dim3(HDIM / 32, DDIM / 32, NE), tb>>>(w1, w1t, DDIM, HDIM);
        transpose_cvt_kernel<<<dim3(DDIM / 32, HDIM / 32, NE), tb>>>(w2, w2t, HDIM, DDIM);
    }

    cudaFuncSetAttribute(gemm_tf32_v9<DDIM, true, false>,
                         cudaFuncAttributeMaxDynamicSharedMemorySize, SMEM_BYTES);
    cudaFuncSetAttribute(gemm_tf32_v9<HDIM, false, true>,
                         cudaFuncAttributeMaxDynamicSharedMemorySize, SMEM_BYTES);

    // GEMM1: hidden = rna(GELU(x @ w1 + b1)); NT=32 -> bulk prefetch schedule
    dim3 g1(HDIM / BN, NTOK / BM, NE);
    gemm_tf32_v9<DDIM, true, false><<<g1, 128, SMEM_BYTES>>>(
        xc, w1t, b1, hidden, HDIM,
        (size_t)NTOK * DDIM, (size_t)DDIM * HDIM, (size_t)NTOK * HDIM);

    // GEMM2: out = hidden @ w2 + b2; NT=128 -> spread prefetch schedule
    dim3 g2(DDIM / BN, NTOK / BM, NE);
    gemm_tf32_v9<HDIM, false, true><<<g2, 128, SMEM_BYTES>>>(
        hidden, w2t, b2, out, DDIM,
        (size_t)NTOK * HDIM, (size_t)HDIM * DDIM, (size_t)NTOK * DDIM);
}